// round 1
// baseline (speedup 1.0000x reference)
#include <cuda_runtime.h>

#define B_   4
#define SM_  1024
#define SI_  4096
#define D_   256
#define H_   8
#define FF_  1024
#define MROWS (B_*SM_)   // 4096
#define IROWS (B_*SI_)   // 16384

// ---------------- scratch (static device globals; no allocs allowed) -------
__device__ float g_ik[IROWS*D_];
__device__ float g_iv[IROWS*D_];
__device__ float g_mk[MROWS*D_];
__device__ float g_mv[MROWS*D_];
__device__ float g_q [H_*MROWS*D_];
__device__ float g_cc[MROWS*H_*D_];
__device__ float g_y [MROWS*D_];
__device__ float g_x [MROWS*D_];
__device__ float g_h [MROWS*FF_];
__device__ float g_g [MROWS*FF_];
__device__ float g_y2[MROWS*D_];

// ---------------- generic tiled GEMM: C = A[M,K] @ B[K,N] + bias ----------
// EPI: 0 = bias only, 1 = bias+relu, 2 = bias + residual R
// batched over blockIdx.z with strides sB (B), sBias, sC.
template<int EPI>
__global__ void gemm64(const float* __restrict__ A, const float* __restrict__ Bm,
                       const float* __restrict__ bias, const float* __restrict__ R,
                       float* __restrict__ C, int M, int N, int K,
                       int sB, int sBias, int sC)
{
    const int z = blockIdx.z;
    Bm   += (size_t)z * sB;
    bias += (size_t)z * sBias;
    C    += (size_t)z * sC;

    const int m0 = blockIdx.y * 64;
    const int n0 = blockIdx.x * 64;
    __shared__ float As[16][64];
    __shared__ float Bs[16][64];

    const int tid = threadIdx.x;
    const int ar = tid >> 2;          // 0..63
    const int ac = (tid & 3) << 2;    // 0,4,8,12
    const int br = tid >> 4;          // 0..15
    const int bc = (tid & 15) << 2;   // 0..60
    const int tm = (tid >> 4) << 2;   // 0..60
    const int tn = (tid & 15) << 2;   // 0..60

    float acc[4][4] = {};
    const float* Ap = A  + (size_t)(m0 + ar) * K + ac;
    const float* Bp = Bm + (size_t)br * N + (n0 + bc);

    for (int k0 = 0; k0 < K; k0 += 16) {
        float4 av = *(const float4*)Ap;  Ap += 16;
        float4 bv = *(const float4*)Bp;  Bp += (size_t)16 * N;
        As[ac+0][ar] = av.x; As[ac+1][ar] = av.y;
        As[ac+2][ar] = av.z; As[ac+3][ar] = av.w;
        *(float4*)&Bs[br][bc] = bv;
        __syncthreads();
        #pragma unroll
        for (int kk = 0; kk < 16; ++kk) {
            float4 a = *(const float4*)&As[kk][tm];
            float4 b = *(const float4*)&Bs[kk][tn];
            acc[0][0] += a.x*b.x; acc[0][1] += a.x*b.y; acc[0][2] += a.x*b.z; acc[0][3] += a.x*b.w;
            acc[1][0] += a.y*b.x; acc[1][1] += a.y*b.y; acc[1][2] += a.y*b.z; acc[1][3] += a.y*b.w;
            acc[2][0] += a.z*b.x; acc[2][1] += a.z*b.y; acc[2][2] += a.z*b.z; acc[2][3] += a.z*b.w;
            acc[3][0] += a.w*b.x; acc[3][1] += a.w*b.y; acc[3][2] += a.w*b.z; acc[3][3] += a.w*b.w;
        }
        __syncthreads();
    }

    const float4 bsv = *(const float4*)&bias[n0 + tn];
    #pragma unroll
    for (int i = 0; i < 4; ++i) {
        const size_t off = (size_t)(m0 + tm + i) * N + (n0 + tn);
        float4 v;
        v.x = acc[i][0] + bsv.x; v.y = acc[i][1] + bsv.y;
        v.z = acc[i][2] + bsv.z; v.w = acc[i][3] + bsv.w;
        if (EPI == 1) {
            v.x = fmaxf(v.x, 0.f); v.y = fmaxf(v.y, 0.f);
            v.z = fmaxf(v.z, 0.f); v.w = fmaxf(v.w, 0.f);
        }
        if (EPI == 2) {
            float4 r = *(const float4*)&R[off];
            v.x += r.x; v.y += r.y; v.z += r.z; v.w += r.w;
        }
        *(float4*)&C[off] = v;
    }
}

// ---------------- fused dual GEMM for the FF gate -------------------------
// C = relu(A@B1 + b1) * (A@B2 + b2)
__global__ void dualgemm64(const float* __restrict__ A,
                           const float* __restrict__ B1, const float* __restrict__ b1,
                           const float* __restrict__ B2, const float* __restrict__ b2,
                           float* __restrict__ C, int M, int N, int K)
{
    const int m0 = blockIdx.y * 64;
    const int n0 = blockIdx.x * 64;
    __shared__ float As [16][64];
    __shared__ float Bs1[16][64];
    __shared__ float Bs2[16][64];

    const int tid = threadIdx.x;
    const int ar = tid >> 2;
    const int ac = (tid & 3) << 2;
    const int br = tid >> 4;
    const int bc = (tid & 15) << 2;
    const int tm = (tid >> 4) << 2;
    const int tn = (tid & 15) << 2;

    float acc1[4][4] = {};
    float acc2[4][4] = {};
    const float* Ap  = A  + (size_t)(m0 + ar) * K + ac;
    const float* Bp1 = B1 + (size_t)br * N + (n0 + bc);
    const float* Bp2 = B2 + (size_t)br * N + (n0 + bc);

    for (int k0 = 0; k0 < K; k0 += 16) {
        float4 av  = *(const float4*)Ap;   Ap  += 16;
        float4 bv1 = *(const float4*)Bp1;  Bp1 += (size_t)16 * N;
        float4 bv2 = *(const float4*)Bp2;  Bp2 += (size_t)16 * N;
        As[ac+0][ar] = av.x; As[ac+1][ar] = av.y;
        As[ac+2][ar] = av.z; As[ac+3][ar] = av.w;
        *(float4*)&Bs1[br][bc] = bv1;
        *(float4*)&Bs2[br][bc] = bv2;
        __syncthreads();
        #pragma unroll
        for (int kk = 0; kk < 16; ++kk) {
            float4 a  = *(const float4*)&As [kk][tm];
            float4 c1 = *(const float4*)&Bs1[kk][tn];
            float4 c2 = *(const float4*)&Bs2[kk][tn];
            acc1[0][0]+=a.x*c1.x; acc1[0][1]+=a.x*c1.y; acc1[0][2]+=a.x*c1.z; acc1[0][3]+=a.x*c1.w;
            acc1[1][0]+=a.y*c1.x; acc1[1][1]+=a.y*c1.y; acc1[1][2]+=a.y*c1.z; acc1[1][3]+=a.y*c1.w;
            acc1[2][0]+=a.z*c1.x; acc1[2][1]+=a.z*c1.y; acc1[2][2]+=a.z*c1.z; acc1[2][3]+=a.z*c1.w;
            acc1[3][0]+=a.w*c1.x; acc1[3][1]+=a.w*c1.y; acc1[3][2]+=a.w*c1.z; acc1[3][3]+=a.w*c1.w;
            acc2[0][0]+=a.x*c2.x; acc2[0][1]+=a.x*c2.y; acc2[0][2]+=a.x*c2.z; acc2[0][3]+=a.x*c2.w;
            acc2[1][0]+=a.y*c2.x; acc2[1][1]+=a.y*c2.y; acc2[1][2]+=a.y*c2.z; acc2[1][3]+=a.y*c2.w;
            acc2[2][0]+=a.z*c2.x; acc2[2][1]+=a.z*c2.y; acc2[2][2]+=a.z*c2.z; acc2[2][3]+=a.z*c2.w;
            acc2[3][0]+=a.w*c2.x; acc2[3][1]+=a.w*c2.y; acc2[3][2]+=a.w*c2.z; acc2[3][3]+=a.w*c2.w;
        }
        __syncthreads();
    }

    const float4 b1v = *(const float4*)&b1[n0 + tn];
    const float4 b2v = *(const float4*)&b2[n0 + tn];
    #pragma unroll
    for (int i = 0; i < 4; ++i) {
        const size_t off = (size_t)(m0 + tm + i) * N + (n0 + tn);
        float4 v;
        v.x = fmaxf(acc1[i][0] + b1v.x, 0.f) * (acc2[i][0] + b2v.x);
        v.y = fmaxf(acc1[i][1] + b1v.y, 0.f) * (acc2[i][1] + b2v.y);
        v.z = fmaxf(acc1[i][2] + b1v.z, 0.f) * (acc2[i][2] + b2v.z);
        v.w = fmaxf(acc1[i][3] + b1v.w, 0.f) * (acc2[i][3] + b2v.w);
        *(float4*)&C[off] = v;
    }
}

// ---------------- flash attention with self-token init --------------------
// grid (SM/32, H, B), 256 threads. Tiles: Q/K/V 32x256 f32 in smem, swizzled.
#define FLASH_SMEM (3*32*256*4 + 32*33*4)

__global__ void __launch_bounds__(256, 2) flash_attn()
{
    const int mt = blockIdx.x, h = blockIdx.y, b = blockIdx.z;
    const int m0 = mt * 32;
    extern __shared__ float smf[];
    float4* QsF = (float4*)smf;          // 32 rows x 64 float4, swizzled
    float4* KsF = QsF + 32*64;
    float4* VsF = KsF + 32*64;
    float*  Ss  = (float*)(VsF + 32*64); // 32 x 33
    __shared__ float rmax[32], rsum[32], ralpha[32];

    const int tid = threadIdx.x;

    // load Q tile (swizzle: chunk c of row r -> slot (c+r)&63)
    const float4* qg = (const float4*)(g_q + ((size_t)h*MROWS + (size_t)b*SM_ + m0) * D_);
    for (int i = tid; i < 2048; i += 256) {
        int r = i >> 6, c = i & 63;
        QsF[(r<<6) + ((c + r) & 63)] = qg[i];
    }
    __syncthreads();

    const int mo = tid >> 3;   // owned query row for self/O phases
    const int p8 = tid & 7;

    // self score init: rmax = s_self/16, rsum = 1 (exp(0)), O = mv row
    {
        const float4* mkg = (const float4*)(g_mk + ((size_t)b*SM_ + m0 + mo) * D_);
        float s = 0.f;
        #pragma unroll
        for (int c = 0; c < 8; ++c) {
            int ch = (p8 << 3) + c;
            float4 q4 = QsF[(mo<<6) + ((ch + mo) & 63)];
            float4 k4 = mkg[ch];
            s += q4.x*k4.x + q4.y*k4.y + q4.z*k4.z + q4.w*k4.w;
        }
        s += __shfl_xor_sync(0xffffffffu, s, 4, 8);
        s += __shfl_xor_sync(0xffffffffu, s, 2, 8);
        s += __shfl_xor_sync(0xffffffffu, s, 1, 8);
        if (p8 == 0) { rmax[mo] = s * 0.0625f; rsum[mo] = 1.f; }
    }
    float4 o[8];
    {
        const float4* mvg = (const float4*)(g_mv + ((size_t)b*SM_ + m0 + mo) * D_);
        #pragma unroll
        for (int c = 0; c < 8; ++c) o[c] = mvg[p8 + (c << 3)];
    }
    __syncthreads();

    const int sown = tid & 31;        // score phase: this thread's key index
    const int mg4  = (tid >> 5) << 2; // and 4 query rows

    for (int s0 = 0; s0 < SI_; s0 += 32) {
        // load K,V tiles
        const float4* kg = (const float4*)(g_ik + ((size_t)b*SI_ + s0) * D_);
        const float4* vg = (const float4*)(g_iv + ((size_t)b*SI_ + s0) * D_);
        for (int i = tid; i < 2048; i += 256) {
            int r = i >> 6, c = i & 63;
            int sw = (r<<6) + ((c + r) & 63);
            KsF[sw] = kg[i];
            VsF[sw] = vg[i];
        }
        __syncthreads();

        // scores: S[m, sown] for m = mg4..mg4+3
        float sc0 = 0.f, sc1 = 0.f, sc2 = 0.f, sc3 = 0.f;
        #pragma unroll 8
        for (int c = 0; c < 64; ++c) {
            float4 k4 = KsF[(sown<<6) + ((c + sown) & 63)];
            float4 q0 = QsF[((mg4+0)<<6) + ((c + mg4+0) & 63)];
            float4 q1 = QsF[((mg4+1)<<6) + ((c + mg4+1) & 63)];
            float4 q2 = QsF[((mg4+2)<<6) + ((c + mg4+2) & 63)];
            float4 q3 = QsF[((mg4+3)<<6) + ((c + mg4+3) & 63)];
            sc0 += q0.x*k4.x + q0.y*k4.y + q0.z*k4.z + q0.w*k4.w;
            sc1 += q1.x*k4.x + q1.y*k4.y + q1.z*k4.z + q1.w*k4.w;
            sc2 += q2.x*k4.x + q2.y*k4.y + q2.z*k4.z + q2.w*k4.w;
            sc3 += q3.x*k4.x + q3.y*k4.y + q3.z*k4.z + q3.w*k4.w;
        }
        Ss[(mg4+0)*33 + sown] = sc0 * 0.0625f;
        Ss[(mg4+1)*33 + sown] = sc1 * 0.0625f;
        Ss[(mg4+2)*33 + sown] = sc2 * 0.0625f;
        Ss[(mg4+3)*33 + sown] = sc3 * 0.0625f;
        __syncthreads();

        // online softmax per row
        if (tid < 32) {
            const int m = tid;
            float mx = rmax[m];
            float nm = mx;
            #pragma unroll
            for (int s = 0; s < 32; ++s) nm = fmaxf(nm, Ss[m*33 + s]);
            float alpha = __expf(mx - nm);
            float sum = rsum[m] * alpha;
            #pragma unroll
            for (int s = 0; s < 32; ++s) {
                float p = __expf(Ss[m*33 + s] - nm);
                Ss[m*33 + s] = p;
                sum += p;
            }
            rmax[m] = nm; rsum[m] = sum; ralpha[m] = alpha;
        }
        __syncthreads();

        // O update: o[m, :] = o*alpha + P @ V
        const float alpha = ralpha[mo];
        #pragma unroll
        for (int c = 0; c < 8; ++c) {
            o[c].x *= alpha; o[c].y *= alpha; o[c].z *= alpha; o[c].w *= alpha;
        }
        #pragma unroll 4
        for (int s = 0; s < 32; ++s) {
            const float p = Ss[mo*33 + s];
            #pragma unroll
            for (int c = 0; c < 8; ++c) {
                float4 v4 = VsF[(s<<6) + ((p8 + (c<<3) + s) & 63)];
                o[c].x += p*v4.x; o[c].y += p*v4.y; o[c].z += p*v4.z; o[c].w += p*v4.w;
            }
        }
        __syncthreads();
    }

    // write concat[b, m, h*D + d]
    const float inv = 1.f / rsum[mo];
    float4* cg = (float4*)(g_cc + (size_t)(b*SM_ + m0 + mo) * (H_*D_) + h*D_);
    #pragma unroll
    for (int c = 0; c < 8; ++c) {
        float4 v = o[c];
        v.x *= inv; v.y *= inv; v.z *= inv; v.w *= inv;
        cg[p8 + (c << 3)] = v;
    }
}

// ---------------- LayerNorm over last dim (256), one block per row --------
__global__ void ln_kernel(const float* __restrict__ Y, const float* __restrict__ g,
                          const float* __restrict__ bb, float* __restrict__ X)
{
    const int row = blockIdx.x;
    const int t = threadIdx.x;
    const float v = Y[(size_t)row*D_ + t];
    __shared__ float red[8];
    __shared__ float stat;

    float s = v;
    #pragma unroll
    for (int o = 16; o; o >>= 1) s += __shfl_xor_sync(0xffffffffu, s, o);
    if ((t & 31) == 0) red[t >> 5] = s;
    __syncthreads();
    if (t == 0) {
        float tot = 0.f;
        #pragma unroll
        for (int i = 0; i < 8; ++i) tot += red[i];
        stat = tot * (1.f / D_);
    }
    __syncthreads();
    const float mean = stat;
    const float d = v - mean;

    s = d * d;
    #pragma unroll
    for (int o = 16; o; o >>= 1) s += __shfl_xor_sync(0xffffffffu, s, o);
    __syncthreads();
    if ((t & 31) == 0) red[t >> 5] = s;
    __syncthreads();
    if (t == 0) {
        float tot = 0.f;
        #pragma unroll
        for (int i = 0; i < 8; ++i) tot += red[i];
        stat = tot * (1.f / D_);
    }
    __syncthreads();
    X[(size_t)row*D_ + t] = d * rsqrtf(stat + 1e-6f) * g[t] + bb[t];
}

// ---------------- launch ---------------------------------------------------
extern "C" void kernel_launch(void* const* d_in, const int* in_sizes, int n_in,
                              void* d_out, int out_size)
{
    (void)in_sizes; (void)n_in; (void)out_size;
    const float* state = (const float*)d_in[0];
    const float* input = (const float*)d_in[1];
    const float* Wk    = (const float*)d_in[2];
    const float* bk    = (const float*)d_in[3];
    const float* Wv    = (const float*)d_in[4];
    const float* bv    = (const float*)d_in[5];
    const float* Wq    = (const float*)d_in[6];
    const float* bq    = (const float*)d_in[7];
    const float* Wo    = (const float*)d_in[8];
    const float* bo    = (const float*)d_in[9];
    const float* ln1g  = (const float*)d_in[10];
    const float* ln1b  = (const float*)d_in[11];
    const float* Win   = (const float*)d_in[12];
    const float* bin   = (const float*)d_in[13];
    const float* Wgnl  = (const float*)d_in[14];
    const float* bgnl  = (const float*)d_in[15];
    const float* Wgl   = (const float*)d_in[16];
    const float* bgl   = (const float*)d_in[17];
    const float* Wgo   = (const float*)d_in[18];
    const float* bgo   = (const float*)d_in[19];
    const float* ln2g  = (const float*)d_in[20];
    const float* ln2b  = (const float*)d_in[21];
    float* out = (float*)d_out;

    float *ik, *iv, *mk, *mv, *qq, *cc, *y, *x, *hb, *gb, *y2;
    cudaGetSymbolAddress((void**)&ik, g_ik);
    cudaGetSymbolAddress((void**)&iv, g_iv);
    cudaGetSymbolAddress((void**)&mk, g_mk);
    cudaGetSymbolAddress((void**)&mv, g_mv);
    cudaGetSymbolAddress((void**)&qq, g_q);
    cudaGetSymbolAddress((void**)&cc, g_cc);
    cudaGetSymbolAddress((void**)&y,  g_y);
    cudaGetSymbolAddress((void**)&x,  g_x);
    cudaGetSymbolAddress((void**)&hb, g_h);
    cudaGetSymbolAddress((void**)&gb, g_g);
    cudaGetSymbolAddress((void**)&y2, g_y2);

    cudaFuncSetAttribute(flash_attn, cudaFuncAttributeMaxDynamicSharedMemorySize, FLASH_SMEM);

    dim3 blk(256);
    // projections
    gemm64<0><<<dim3(D_/64, IROWS/64), blk>>>(input, Wk, bk, nullptr, ik, IROWS, D_, D_, 0, 0, 0);
    gemm64<0><<<dim3(D_/64, IROWS/64), blk>>>(input, Wv, bv, nullptr, iv, IROWS, D_, D_, 0, 0, 0);
    gemm64<0><<<dim3(D_/64, MROWS/64), blk>>>(state, Wk, bk, nullptr, mk, MROWS, D_, D_, 0, 0, 0);
    gemm64<0><<<dim3(D_/64, MROWS/64), blk>>>(state, Wv, bv, nullptr, mv, MROWS, D_, D_, 0, 0, 0);
    // per-head Q (batched over z)
    gemm64<0><<<dim3(D_/64, MROWS/64, H_), blk>>>(state, Wq, bq, nullptr, qq,
                                                  MROWS, D_, D_, D_*D_, D_, MROWS*D_);
    // flash attention -> concat
    flash_attn<<<dim3(SM_/32, H_, B_), blk, FLASH_SMEM>>>();
    // output proj + residual, LN1
    gemm64<2><<<dim3(D_/64, MROWS/64), blk>>>(cc, Wo, bo, state, y, MROWS, D_, H_*D_, 0, 0, 0);
    ln_kernel<<<MROWS, D_>>>(y, ln1g, ln1b, x);
    // FFN
    gemm64<1><<<dim3(FF_/64, MROWS/64), blk>>>(x, Win, bin, nullptr, hb, MROWS, FF_, D_, 0, 0, 0);
    dualgemm64<<<dim3(FF_/64, MROWS/64), blk>>>(hb, Wgnl, bgnl, Wgl, bgl, gb, MROWS, FF_, FF_);
    gemm64<2><<<dim3(D_/64, MROWS/64), blk>>>(gb, Wgo, bgo, x, y2, MROWS, D_, FF_, 0, 0, 0);
    ln_kernel<<<MROWS, D_>>>(y2, ln2g, ln2b, out);
}

// round 2
// speedup vs baseline: 10.2072x; 10.2072x over previous
#include <cuda_runtime.h>
#include <cuda_bf16.h>
#include <cstdint>

#define B_   4
#define SM_  1024
#define SI_  4096
#define D_   256
#define H_   8
#define FF_  1024
#define MROWS (B_*SM_)   // 4096
#define IROWS (B_*SI_)   // 16384

typedef __nv_bfloat16  bf16;
typedef __nv_bfloat162 bf162;

// ---------------- scratch (static device globals) --------------------------
__device__ bf16  g_ib  [IROWS*D_];
__device__ bf16  g_sb  [MROWS*D_];
__device__ bf16  g_Wkb [D_*D_];
__device__ bf16  g_Wvb [D_*D_];
__device__ bf16  g_Wqb [H_*D_*D_];
__device__ bf16  g_Wob [H_*D_*D_];
__device__ bf16  g_Winb[D_*FF_];
__device__ bf16  g_Wgnlb[FF_*FF_];
__device__ bf16  g_Wglb [FF_*FF_];
__device__ bf16  g_Wgob [FF_*D_];
__device__ bf16  g_ikb [IROWS*D_];
__device__ bf16  g_ivb [IROWS*D_];
__device__ bf16  g_mkb [MROWS*D_];
__device__ float g_mvf [MROWS*D_];
__device__ bf16  g_qb  [H_*MROWS*D_];
__device__ bf16  g_ccb [MROWS*H_*D_];
__device__ float g_y   [MROWS*D_];
__device__ float g_x   [MROWS*D_];
__device__ bf16  g_xb  [MROWS*D_];
__device__ bf16  g_hb  [MROWS*FF_];
__device__ float g_t1  [MROWS*FF_];
__device__ float g_t2  [MROWS*FF_];
__device__ bf16  g_gb  [MROWS*FF_];
__device__ float g_y2  [MROWS*D_];

// ---------------- PTX helpers ----------------------------------------------
__device__ __forceinline__ uint32_t sptr(const void* p){
    return (uint32_t)__cvta_generic_to_shared(p);
}
__device__ __forceinline__ void ldsm4(uint32_t a[4], uint32_t addr){
    asm volatile("ldmatrix.sync.aligned.m8n8.x4.shared.b16 {%0,%1,%2,%3},[%4];"
        : "=r"(a[0]),"=r"(a[1]),"=r"(a[2]),"=r"(a[3]) : "r"(addr));
}
__device__ __forceinline__ void ldsm4t(uint32_t a[4], uint32_t addr){
    asm volatile("ldmatrix.sync.aligned.m8n8.x4.trans.shared.b16 {%0,%1,%2,%3},[%4];"
        : "=r"(a[0]),"=r"(a[1]),"=r"(a[2]),"=r"(a[3]) : "r"(addr));
}
__device__ __forceinline__ void mma16816(float c[4], const uint32_t a[4], const uint32_t b[2]){
    asm volatile("mma.sync.aligned.m16n8k16.row.col.f32.bf16.bf16.f32 "
        "{%0,%1,%2,%3},{%4,%5,%6,%7},{%8,%9},{%0,%1,%2,%3};"
        : "+f"(c[0]),"+f"(c[1]),"+f"(c[2]),"+f"(c[3])
        : "r"(a[0]),"r"(a[1]),"r"(a[2]),"r"(a[3]),"r"(b[0]),"r"(b[1]));
}
__device__ __forceinline__ void cp16(uint32_t dst, const void* src){
    asm volatile("cp.async.cg.shared.global [%0],[%1],16;" :: "r"(dst),"l"(src));
}
__device__ __forceinline__ void cpcommit(){ asm volatile("cp.async.commit_group;"); }
__device__ __forceinline__ void cpwait0(){ asm volatile("cp.async.wait_group 0;"); }
__device__ __forceinline__ void cpwait1(){ asm volatile("cp.async.wait_group 1;"); }

// ---------------- convert fp32 -> bf16 -------------------------------------
__global__ void cvt_bf16(const float* __restrict__ s, bf16* __restrict__ d, int n){
    int i = (blockIdx.x*blockDim.x + threadIdx.x)*4;
    if (i < n){
        float4 v = *(const float4*)(s+i);
        *(bf162*)(d+i)   = __floats2bfloat162_rn(v.x, v.y);
        *(bf162*)(d+i+2) = __floats2bfloat162_rn(v.z, v.w);
    }
}

// ---------------- bf16 GEMM: C = A[M,K] @ B[K,N] + bias --------------------
// OUTMODE: 0 bf16, 1 bf16+relu, 2 f32, 3 f32+residual R
template<int OUTMODE>
__global__ void __launch_bounds__(256) gemm_bf(
    const bf16* __restrict__ A, const bf16* __restrict__ Bw,
    const float* __restrict__ bias, const float* __restrict__ R,
    void* __restrict__ Cout, int M, int N, int K,
    long sB, long sBias, long sC)
{
    __shared__ __align__(16) bf16 smA[2][128*32];
    __shared__ __align__(16) bf16 smB[2][32*128];

    const int z = blockIdx.z;
    Bw   += (size_t)z*sB;
    bias += (size_t)z*sBias;

    const int m0 = blockIdx.y*128, n0 = blockIdx.x*128;
    const int t = threadIdx.x;
    const int w = t>>5, lane = t&31;
    const int wm = w>>1, wn = w&1;

    auto loadA = [&](int st, int k0){
        #pragma unroll
        for (int i=0;i<2;++i){
            int idx = t + i*256;             // 0..511
            int r = idx>>2, c = idx&3;
            int csw = c ^ ((r>>1)&3);
            cp16(sptr(&smA[st][(r*4+csw)*8]), A + (size_t)(m0+r)*K + k0 + c*8);
        }
    };
    auto loadB = [&](int st, int k0){
        #pragma unroll
        for (int i=0;i<2;++i){
            int idx = t + i*256;
            int r = idx>>4, c = idx&15;
            int csw = c ^ (r&7);
            cp16(sptr(&smB[st][(r*16+csw)*8]), Bw + (size_t)(k0+r)*N + n0 + c*8);
        }
    };

    float acc[2][8][4] = {};

    loadA(0,0); loadB(0,0); cpcommit();
    const int KT = K>>5;
    for (int kt=0; kt<KT; ++kt){
        int st = kt&1;
        if (kt+1<KT){ loadA(st^1,(kt+1)*32); loadB(st^1,(kt+1)*32); cpcommit(); cpwait1(); }
        else cpwait0();
        __syncthreads();

        #pragma unroll
        for (int ks=0; ks<2; ++ks){
            uint32_t af[2][4];
            #pragma unroll
            for (int mt=0; mt<2; ++mt){
                int r = wm*32 + mt*16 + (lane&7) + ((lane>>3)&1)*8;
                int c = ks*2 + (lane>>4);
                int csw = c ^ ((r>>1)&3);
                ldsm4(af[mt], sptr(&smA[st][(r*4+csw)*8]));
            }
            #pragma unroll
            for (int np=0; np<4; ++np){
                uint32_t bfr[4];
                int kr = ks*16 + (lane&7) + ((lane>>3)&1)*8;
                int c  = (wn*64 + np*16)/8 + (lane>>4);
                int csw = c ^ (kr&7);
                ldsm4t(bfr, sptr(&smB[st][(kr*16+csw)*8]));
                mma16816(acc[0][np*2+0], af[0], &bfr[0]);
                mma16816(acc[0][np*2+1], af[0], &bfr[2]);
                mma16816(acc[1][np*2+0], af[1], &bfr[0]);
                mma16816(acc[1][np*2+1], af[1], &bfr[2]);
            }
        }
        __syncthreads();
    }

    const int rbase = m0 + wm*32 + (lane>>2);
    const int cbase = n0 + wn*64 + (lane&3)*2;
    #pragma unroll
    for (int mt=0; mt<2; ++mt){
        #pragma unroll
        for (int nt=0; nt<8; ++nt){
            int row = rbase + mt*16;
            int col = cbase + nt*8;
            float b0 = bias[col], b1 = bias[col+1];
            float v0 = acc[mt][nt][0]+b0, v1 = acc[mt][nt][1]+b1;
            float v2 = acc[mt][nt][2]+b0, v3 = acc[mt][nt][3]+b1;
            if (OUTMODE==1){
                v0=fmaxf(v0,0.f); v1=fmaxf(v1,0.f); v2=fmaxf(v2,0.f); v3=fmaxf(v3,0.f);
            }
            if (OUTMODE==3){
                float2 r0 = *(const float2*)(R + (size_t)row*N + col);
                float2 r1 = *(const float2*)(R + (size_t)(row+8)*N + col);
                v0+=r0.x; v1+=r0.y; v2+=r1.x; v3+=r1.y;
            }
            if (OUTMODE<=1){
                bf16* C = (bf16*)Cout + (size_t)z*sC;
                *(bf162*)(C + (size_t)row*N + col)     = __floats2bfloat162_rn(v0,v1);
                *(bf162*)(C + (size_t)(row+8)*N + col) = __floats2bfloat162_rn(v2,v3);
            } else {
                float* C = (float*)Cout + (size_t)z*sC;
                *(float2*)(C + (size_t)row*N + col)     = make_float2(v0,v1);
                *(float2*)(C + (size_t)(row+8)*N + col) = make_float2(v2,v3);
            }
        }
    }
}

// ---------------- flash attention (bf16 HMMA) -------------------------------
// Q tile 64 rows, K/V tiles 64 keys, D=256. Self-token folded into init state.
#define FL_K(st) (32768 + (st)*65536)
#define FL_V(st) (65536 + (st)*65536)
#define FL_P 163840
#define FL_STAT 173056
#define FLASH_SMEM (174848 + 256)

__global__ void __launch_bounds__(256,1) flash_bf()
{
    extern __shared__ __align__(16) char sm[];
    bf16*  Qs = (bf16*)(sm);
    bf16*  Ps = (bf16*)(sm + FL_P);           // [64][72]
    float* rmax   = (float*)(sm + FL_STAT);
    float* rsum   = rmax + 64;
    float* ralpha = rsum + 64;
    float* pmax   = ralpha + 64;              // [64][2]
    float* psum   = pmax + 128;               // [64][2]

    const int t = threadIdx.x, w = t>>5, lane = t&31;
    const int h = blockIdx.y, b = blockIdx.z;
    const int m0 = blockIdx.x*64;

    auto qkvoff = [](int r, int c){ return (r*32 + (c ^ (r&7)))*8; };

    // Q load (+ tile0, tile1 prefetch)
    const bf16* qg = g_qb + ((size_t)h*MROWS + (size_t)b*SM_ + m0)*D_;
    #pragma unroll
    for (int i=0;i<8;++i){
        int idx = t + i*256;
        int r = idx>>5, c = idx&31;
        cp16(sptr(Qs + qkvoff(r,c)), qg + (size_t)r*D_ + c*8);
    }
    auto loadKV = [&](int tile, int st){
        const bf16* kg = g_ikb + ((size_t)b*SI_ + tile*64)*D_;
        const bf16* vg = g_ivb + ((size_t)b*SI_ + tile*64)*D_;
        bf16* Ks = (bf16*)(sm + FL_K(st));
        bf16* Vs = (bf16*)(sm + FL_V(st));
        #pragma unroll
        for (int i=0;i<8;++i){
            int idx = t + i*256;
            int r = idx>>5, c = idx&31;
            int off = qkvoff(r,c);
            cp16(sptr(Ks + off), kg + (size_t)r*D_ + c*8);
            cp16(sptr(Vs + off), vg + (size_t)r*D_ + c*8);
        }
    };
    loadKV(0,0); cpcommit();
    loadKV(1,1); cpcommit();
    cpwait1(); __syncthreads();   // Q + tile0 ready

    // self-score init: rmax = (q . mk)/16, rsum = 1
    {
        int row = t>>2, quad = t&3;
        const bf16* mk = g_mkb + ((size_t)b*SM_ + m0 + row)*D_;
        float s = 0.f;
        #pragma unroll
        for (int cc=0; cc<8; ++cc){
            int c = quad*8 + cc;
            const bf162* q2 = (const bf162*)(Qs + qkvoff(row,c));
            const bf162* k2 = (const bf162*)(mk + c*8);
            #pragma unroll
            for (int j=0;j<4;++j){
                float2 qv = __bfloat1622float2(q2[j]);
                float2 kv = __bfloat1622float2(k2[j]);
                s += qv.x*kv.x + qv.y*kv.y;
            }
        }
        s += __shfl_xor_sync(~0u, s, 1);
        s += __shfl_xor_sync(~0u, s, 2);
        if (quad==0){ rmax[row] = s*0.0625f; rsum[row] = 1.f; }
    }

    // O init = mv (fp32)
    const int mh = w>>2, nq = w&3;
    float o[2][8][4];
    {
        const float* mv = g_mvf + ((size_t)b*SM_ + m0)*D_;
        #pragma unroll
        for (int mt=0;mt<2;++mt){
            int r0 = mh*32 + mt*16 + (lane>>2);
            #pragma unroll
            for (int nt=0;nt<8;++nt){
                int col = nq*64 + nt*8 + (lane&3)*2;
                float2 v0 = *(const float2*)(mv + (size_t)r0*D_ + col);
                float2 v1 = *(const float2*)(mv + (size_t)(r0+8)*D_ + col);
                o[mt][nt][0]=v0.x; o[mt][nt][1]=v0.y; o[mt][nt][2]=v1.x; o[mt][nt][3]=v1.y;
            }
        }
    }
    __syncthreads();

    const int sw_m = w>>1, sw_n = w&1;
    const int NT = SI_/64;

    for (int tile=0; tile<NT; ++tile){
        int st = tile&1;
        bf16* Ks = (bf16*)(sm + FL_K(st));
        bf16* Vs = (bf16*)(sm + FL_V(st));

        // S = Q @ K^T (warp: 16 rows x 32 keys)
        float sa[4][4] = {};
        #pragma unroll
        for (int ks=0; ks<16; ++ks){
            uint32_t af[4];
            {
                int r = sw_m*16 + (lane&7) + ((lane>>3)&1)*8;
                int c = ks*2 + (lane>>4);
                ldsm4(af, sptr(Qs + qkvoff(r,c)));
            }
            #pragma unroll
            for (int np=0; np<2; ++np){
                uint32_t bfr[4];
                int r = sw_n*32 + np*16 + (lane&7) + ((lane>>4)&1)*8;
                int c = ks*2 + ((lane>>3)&1);
                ldsm4(bfr, sptr(Ks + qkvoff(r,c)));
                mma16816(sa[np*2+0], af, &bfr[0]);
                mma16816(sa[np*2+1], af, &bfr[2]);
            }
        }
        #pragma unroll
        for (int i=0;i<4;++i){
            sa[i][0]*=0.0625f; sa[i][1]*=0.0625f; sa[i][2]*=0.0625f; sa[i][3]*=0.0625f;
        }

        // row max (partial across this warp's 32 cols)
        float mx0 = -1e30f, mx1 = -1e30f;
        #pragma unroll
        for (int i=0;i<4;++i){
            mx0 = fmaxf(mx0, fmaxf(sa[i][0], sa[i][1]));
            mx1 = fmaxf(mx1, fmaxf(sa[i][2], sa[i][3]));
        }
        mx0 = fmaxf(mx0, __shfl_xor_sync(~0u, mx0, 1));
        mx0 = fmaxf(mx0, __shfl_xor_sync(~0u, mx0, 2));
        mx1 = fmaxf(mx1, __shfl_xor_sync(~0u, mx1, 1));
        mx1 = fmaxf(mx1, __shfl_xor_sync(~0u, mx1, 2));
        if ((lane&3)==0){
            int r = sw_m*16 + (lane>>2);
            pmax[r*2 + sw_n] = mx0;
            pmax[(r+8)*2 + sw_n] = mx1;
        }
        __syncthreads();
        if (t < 64){
            float mnew = fmaxf(rmax[t], fmaxf(pmax[t*2], pmax[t*2+1]));
            ralpha[t] = __expf(rmax[t]-mnew);
            rmax[t] = mnew;
        }
        __syncthreads();

        // exp + P store + partial sums
        {
            int r0 = sw_m*16 + (lane>>2);
            float m0r = rmax[r0], m1r = rmax[r0+8];
            float s0 = 0.f, s1 = 0.f;
            #pragma unroll
            for (int i=0;i<4;++i){
                sa[i][0] = __expf(sa[i][0]-m0r); sa[i][1] = __expf(sa[i][1]-m0r);
                sa[i][2] = __expf(sa[i][2]-m1r); sa[i][3] = __expf(sa[i][3]-m1r);
                s0 += sa[i][0]+sa[i][1]; s1 += sa[i][2]+sa[i][3];
                int col = sw_n*32 + i*8 + (lane&3)*2;
                *(bf162*)(Ps + r0*72 + col)     = __floats2bfloat162_rn(sa[i][0], sa[i][1]);
                *(bf162*)(Ps + (r0+8)*72 + col) = __floats2bfloat162_rn(sa[i][2], sa[i][3]);
            }
            s0 += __shfl_xor_sync(~0u,s0,1); s0 += __shfl_xor_sync(~0u,s0,2);
            s1 += __shfl_xor_sync(~0u,s1,1); s1 += __shfl_xor_sync(~0u,s1,2);
            if ((lane&3)==0){ psum[r0*2+sw_n]=s0; psum[(r0+8)*2+sw_n]=s1; }
        }
        __syncthreads();
        if (t<64) rsum[t] = rsum[t]*ralpha[t] + psum[t*2] + psum[t*2+1];

        // O = O*alpha + P @ V  (warp: 32 rows x 64 d-cols)
        #pragma unroll
        for (int mt=0;mt<2;++mt){
            int r0 = mh*32 + mt*16 + (lane>>2);
            float a0 = ralpha[r0], a1 = ralpha[r0+8];
            #pragma unroll
            for (int nt=0;nt<8;++nt){
                o[mt][nt][0]*=a0; o[mt][nt][1]*=a0; o[mt][nt][2]*=a1; o[mt][nt][3]*=a1;
            }
        }
        #pragma unroll
        for (int ks=0; ks<4; ++ks){
            uint32_t af[2][4];
            #pragma unroll
            for (int mt=0;mt<2;++mt){
                int r = mh*32 + mt*16 + (lane&7) + ((lane>>3)&1)*8;
                int c = ks*2 + (lane>>4);
                ldsm4(af[mt], sptr(Ps + r*72 + c*8));
            }
            #pragma unroll
            for (int np=0;np<4;++np){
                uint32_t bfr[4];
                int kr = ks*16 + (lane&7) + ((lane>>3)&1)*8;
                int c  = (nq*64 + np*16)/8 + (lane>>4);
                ldsm4t(bfr, sptr(Vs + qkvoff(kr,c)));
                mma16816(o[0][np*2+0], af[0], &bfr[0]);
                mma16816(o[0][np*2+1], af[0], &bfr[2]);
                mma16816(o[1][np*2+0], af[1], &bfr[0]);
                mma16816(o[1][np*2+1], af[1], &bfr[2]);
            }
        }
        __syncthreads();
        if (tile+2 < NT){ loadKV(tile+2, st); cpcommit(); cpwait1(); }
        else cpwait0();
        __syncthreads();
    }

    // final normalize + write concat (bf16)
    #pragma unroll
    for (int mt=0;mt<2;++mt){
        int r0 = mh*32 + mt*16 + (lane>>2);
        float i0 = 1.f/rsum[r0], i1 = 1.f/rsum[r0+8];
        bf16* c0 = g_ccb + ((size_t)(b*SM_ + m0 + r0)*(H_*D_)) + h*D_;
        bf16* c1 = g_ccb + ((size_t)(b*SM_ + m0 + r0 + 8)*(H_*D_)) + h*D_;
        #pragma unroll
        for (int nt=0;nt<8;++nt){
            int col = nq*64 + nt*8 + (lane&3)*2;
            *(bf162*)(c0+col) = __floats2bfloat162_rn(o[mt][nt][0]*i0, o[mt][nt][1]*i0);
            *(bf162*)(c1+col) = __floats2bfloat162_rn(o[mt][nt][2]*i1, o[mt][nt][3]*i1);
        }
    }
}

// ---------------- LayerNorm (last dim 256), optional bf16 copy --------------
__global__ void ln_kernel(const float* __restrict__ Y, const float* __restrict__ g,
                          const float* __restrict__ bb, float* __restrict__ X,
                          bf16* __restrict__ Xb)
{
    const int row = blockIdx.x;
    const int t = threadIdx.x;
    const float v = Y[(size_t)row*D_ + t];
    __shared__ float red[8];
    __shared__ float stat;

    float s = v;
    #pragma unroll
    for (int o = 16; o; o >>= 1) s += __shfl_xor_sync(0xffffffffu, s, o);
    if ((t & 31) == 0) red[t >> 5] = s;
    __syncthreads();
    if (t == 0) {
        float tot = 0.f;
        #pragma unroll
        for (int i = 0; i < 8; ++i) tot += red[i];
        stat = tot * (1.f / D_);
    }
    __syncthreads();
    const float mean = stat;
    const float d = v - mean;

    s = d * d;
    #pragma unroll
    for (int o = 16; o; o >>= 1) s += __shfl_xor_sync(0xffffffffu, s, o);
    __syncthreads();
    if ((t & 31) == 0) red[t >> 5] = s;
    __syncthreads();
    if (t == 0) {
        float tot = 0.f;
        #pragma unroll
        for (int i = 0; i < 8; ++i) tot += red[i];
        stat = tot * (1.f / D_);
    }
    __syncthreads();
    float out = d * rsqrtf(stat + 1e-6f) * g[t] + bb[t];
    X[(size_t)row*D_ + t] = out;
    if (Xb) Xb[(size_t)row*D_ + t] = __float2bfloat16(out);
}

// ---------------- gate multiply: g = bf16(relu(t1)*t2) ----------------------
__global__ void gate_mult(const float* __restrict__ t1, const float* __restrict__ t2,
                          bf16* __restrict__ gout, int n)
{
    int i = (blockIdx.x*blockDim.x + threadIdx.x)*2;
    if (i < n){
        float2 a = *(const float2*)(t1+i);
        float2 b = *(const float2*)(t2+i);
        *(bf162*)(gout+i) = __floats2bfloat162_rn(fmaxf(a.x,0.f)*b.x, fmaxf(a.y,0.f)*b.y);
    }
}

// ---------------- launch ----------------------------------------------------
extern "C" void kernel_launch(void* const* d_in, const int* in_sizes, int n_in,
                              void* d_out, int out_size)
{
    (void)in_sizes; (void)n_in; (void)out_size;
    const float* state = (const float*)d_in[0];
    const float* input = (const float*)d_in[1];
    const float* Wk    = (const float*)d_in[2];
    const float* bk    = (const float*)d_in[3];
    const float* Wv    = (const float*)d_in[4];
    const float* bv    = (const float*)d_in[5];
    const float* Wq    = (const float*)d_in[6];
    const float* bq    = (const float*)d_in[7];
    const float* Wo    = (const float*)d_in[8];
    const float* bo    = (const float*)d_in[9];
    const float* ln1g  = (const float*)d_in[10];
    const float* ln1b  = (const float*)d_in[11];
    const float* Win   = (const float*)d_in[12];
    const float* bin   = (const float*)d_in[13];
    const float* Wgnl  = (const float*)d_in[14];
    const float* bgnl  = (const float*)d_in[15];
    const float* Wgl   = (const float*)d_in[16];
    const float* bgl   = (const float*)d_in[17];
    const float* Wgo   = (const float*)d_in[18];
    const float* bgo   = (const float*)d_in[19];
    const float* ln2g  = (const float*)d_in[20];
    const float* ln2b  = (const float*)d_in[21];
    float* out = (float*)d_out;

    bf16 *ib,*sb,*Wkb,*Wvb,*Wqb,*Wob,*Winb,*Wgnlb,*Wglb,*Wgob;
    bf16 *ikb,*ivb,*mkb,*qb,*ccb,*xb,*hb,*gb;
    float *mvf,*y,*x,*t1,*t2,*y2;
    cudaGetSymbolAddress((void**)&ib,  g_ib);
    cudaGetSymbolAddress((void**)&sb,  g_sb);
    cudaGetSymbolAddress((void**)&Wkb, g_Wkb);
    cudaGetSymbolAddress((void**)&Wvb, g_Wvb);
    cudaGetSymbolAddress((void**)&Wqb, g_Wqb);
    cudaGetSymbolAddress((void**)&Wob, g_Wob);
    cudaGetSymbolAddress((void**)&Winb,g_Winb);
    cudaGetSymbolAddress((void**)&Wgnlb,g_Wgnlb);
    cudaGetSymbolAddress((void**)&Wglb, g_Wglb);
    cudaGetSymbolAddress((void**)&Wgob, g_Wgob);
    cudaGetSymbolAddress((void**)&ikb, g_ikb);
    cudaGetSymbolAddress((void**)&ivb, g_ivb);
    cudaGetSymbolAddress((void**)&mkb, g_mkb);
    cudaGetSymbolAddress((void**)&mvf, g_mvf);
    cudaGetSymbolAddress((void**)&qb,  g_qb);
    cudaGetSymbolAddress((void**)&ccb, g_ccb);
    cudaGetSymbolAddress((void**)&y,   g_y);
    cudaGetSymbolAddress((void**)&x,   g_x);
    cudaGetSymbolAddress((void**)&xb,  g_xb);
    cudaGetSymbolAddress((void**)&hb,  g_hb);
    cudaGetSymbolAddress((void**)&t1,  g_t1);
    cudaGetSymbolAddress((void**)&t2,  g_t2);
    cudaGetSymbolAddress((void**)&gb,  g_gb);
    cudaGetSymbolAddress((void**)&y2,  g_y2);

    cudaFuncSetAttribute(flash_bf, cudaFuncAttributeMaxDynamicSharedMemorySize, FLASH_SMEM);

    dim3 blk(256);
    auto cvt = [&](const float* s, bf16* d, int n){
        cvt_bf16<<<(n/4 + 255)/256, 256>>>(s, d, n);
    };
    // converts
    cvt(input, ib, IROWS*D_);
    cvt(state, sb, MROWS*D_);
    cvt(Wk,  Wkb,  D_*D_);
    cvt(Wv,  Wvb,  D_*D_);
    cvt(Wq,  Wqb,  H_*D_*D_);
    cvt(Wo,  Wob,  H_*D_*D_);
    cvt(Win, Winb, D_*FF_);
    cvt(Wgnl,Wgnlb,FF_*FF_);
    cvt(Wgl, Wglb, FF_*FF_);
    cvt(Wgo, Wgob, FF_*D_);

    // projections
    gemm_bf<0><<<dim3(D_/128, IROWS/128), blk>>>(ib, Wkb, bk, nullptr, ikb, IROWS, D_, D_, 0,0,0);
    gemm_bf<0><<<dim3(D_/128, IROWS/128), blk>>>(ib, Wvb, bv, nullptr, ivb, IROWS, D_, D_, 0,0,0);
    gemm_bf<0><<<dim3(D_/128, MROWS/128), blk>>>(sb, Wkb, bk, nullptr, mkb, MROWS, D_, D_, 0,0,0);
    gemm_bf<2><<<dim3(D_/128, MROWS/128), blk>>>(sb, Wvb, bv, nullptr, mvf, MROWS, D_, D_, 0,0,0);
    gemm_bf<0><<<dim3(D_/128, MROWS/128, H_), blk>>>(sb, Wqb, bq, nullptr, qb,
                                                     MROWS, D_, D_, (long)D_*D_, D_, (long)MROWS*D_);
    // flash attention
    flash_bf<<<dim3(SM_/64, H_, B_), blk, FLASH_SMEM>>>();
    // output proj + residual, LN1
    gemm_bf<3><<<dim3(D_/128, MROWS/128), blk>>>(ccb, Wob, bo, state, y, MROWS, D_, H_*D_, 0,0,0);
    ln_kernel<<<MROWS, D_>>>(y, ln1g, ln1b, x, xb);
    // FFN
    gemm_bf<1><<<dim3(FF_/128, MROWS/128), blk>>>(xb, Winb, bin, nullptr, hb, MROWS, FF_, D_, 0,0,0);
    gemm_bf<2><<<dim3(FF_/128, MROWS/128), blk>>>(hb, Wgnlb, bgnl, nullptr, t1, MROWS, FF_, FF_, 0,0,0);
    gemm_bf<2><<<dim3(FF_/128, MROWS/128), blk>>>(hb, Wglb,  bgl,  nullptr, t2, MROWS, FF_, FF_, 0,0,0);
    gate_mult<<<(MROWS*FF_/2 + 255)/256, 256>>>(t1, t2, gb, MROWS*FF_);
    gemm_bf<3><<<dim3(D_/128, MROWS/128), blk>>>(gb, Wgob, bgo, x, y2, MROWS, D_, FF_, 0,0,0);
    ln_kernel<<<MROWS, D_>>>(y2, ln2g, ln2b, out, nullptr);
}